// round 8
// baseline (speedup 1.0000x reference)
#include <cuda_runtime.h>
#include <cuda_bf16.h>

#define N_GROUPS 256
#define EMBED 1024
#define VEC4 (EMBED / 4)   // 256 float4 per row
#define KSPLIT 8
#define NPART (N_GROUPS * N_GROUPS)   // 65536
#define CHUNK 16
#define NCHUNK 256          // covers up to 4096 rows; both sources fit

// Scratch (device globals; no allocation allowed)
__device__ float g_im_mean[N_GROUPS * EMBED];
__device__ float g_s_mean[N_GROUPS * EMBED];
__device__ float g_part[2 * N_GROUPS * 3 * EMBED];   // [src][group][slot][1024]
__device__ float g_Spart[KSPLIT * NPART];
__device__ float g_loss_part[64];
__device__ int   g_count;   // zero-init at load; reset by last block each launch

// ---------------------------------------------------------------------------
// Kernel 1a: balanced chunked segment-sum.
// Grid = 2048 blocks x 64 threads. blockIdx.x = c*8 + src*4 + quarter.
// Every block processes EXACTLY 16 rows (last chunk: remainder) of one
// column-quarter: uniform runtime -> flat SM concurrency, no drain tail.
// Rows are classified into <=3 group segments (static accumulators) using the
// in-block prefix scan of counts; partial sums go to g_part[(src,g,slot)].
// ---------------------------------------------------------------------------
__global__ void __launch_bounds__(64) segchunk_kernel(
    const float* __restrict__ im, const float* __restrict__ s,
    const int* __restrict__ num_clips, const int* __restrict__ num_caps)
{
    __shared__ int pref[N_GROUPS];   // inclusive prefix of counts
    __shared__ int wsum[2];

    const int b = blockIdx.x;
    const int c = b >> 3;
    const bool is_im = ((b >> 2) & 1) == 0;
    const int srcI = is_im ? 0 : 1;
    const int quarter = b & 3;
    const int* __restrict__ cnt = is_im ? num_clips : num_caps;
    const float4* __restrict__ src = (const float4*)(is_im ? im : s);

    const int t = threadIdx.x;

    // ---- inclusive prefix scan of 256 counts by 64 threads (4 each) ----
    int c4[4];
    #pragma unroll
    for (int u = 0; u < 4; u++) c4[u] = cnt[t * 4 + u];
    int l0 = c4[0];
    int l1 = l0 + c4[1];
    int l2 = l1 + c4[2];
    int l3 = l2 + c4[3];
    // warp-inclusive scan of l3 over 32 lanes
    int incl = l3;
    #pragma unroll
    for (int o = 1; o < 32; o <<= 1) {
        int v = __shfl_up_sync(0xFFFFFFFFu, incl, o);
        if ((t & 31) >= o) incl += v;
    }
    if ((t & 31) == 31) wsum[t >> 5] = incl;
    __syncthreads();
    int base = incl - l3 + ((t >= 32) ? wsum[0] : 0);
    pref[t * 4 + 0] = base + l0;
    pref[t * 4 + 1] = base + l1;
    pref[t * 4 + 2] = base + l2;
    pref[t * 4 + 3] = base + l3;
    __syncthreads();

    const int total = pref[N_GROUPS - 1];
    const int rbeg = c * CHUNK;
    if (rbeg >= total) return;
    const int rend = min(rbeg + CHUNK, total);
    const int nrows = rend - rbeg;

    // ---- find first group overlapping rbeg: smallest g with pref[g] > rbeg
    int lo = 0, hi = N_GROUPS - 1;
    while (lo < hi) {
        int mid = (lo + hi) >> 1;
        if (pref[mid] > rbeg) hi = mid; else lo = mid + 1;
    }
    const int g0 = lo;
    const int e0 = pref[g0];
    const int e1 = (g0 + 1 < N_GROUPS) ? pref[g0 + 1] : 0x7FFFFFFF;

    // ---- accumulate 16 rows into <=3 segment accumulators ----
    const float4* p = src + (size_t)rbeg * VEC4 + quarter * 64 + t;
    float4 a0 = make_float4(0.f, 0.f, 0.f, 0.f);
    float4 a1 = make_float4(0.f, 0.f, 0.f, 0.f);
    float4 a2 = make_float4(0.f, 0.f, 0.f, 0.f);
    #pragma unroll
    for (int i = 0; i < CHUNK; i++) {
        if (i < nrows) {
            float4 v = p[(size_t)i * VEC4];
            int row = rbeg + i;
            if (row < e0)      { a0.x += v.x; a0.y += v.y; a0.z += v.z; a0.w += v.w; }
            else if (row < e1) { a1.x += v.x; a1.y += v.y; a1.z += v.z; a1.w += v.w; }
            else               { a2.x += v.x; a2.y += v.y; a2.z += v.z; a2.w += v.w; }
        }
    }

    // ---- write partials; slot = chunk - first chunk of that group ----
    const int col4 = quarter * 64 + t;  // float4 index within row
    {
        const int start0 = (g0 == 0) ? 0 : pref[g0 - 1];
        const int slot0 = c - (start0 >> 4);
        float4* w = (float4*)&g_part[(size_t)((srcI * N_GROUPS + g0) * 3 + slot0) * EMBED];
        w[col4] = a0;
    }
    if (e0 < rend) {
        // group g0+1 starts inside this chunk -> slot 0
        float4* w = (float4*)&g_part[(size_t)((srcI * N_GROUPS + g0 + 1) * 3 + 0) * EMBED];
        w[col4] = a1;
    }
    if (e1 < rend) {
        float4* w = (float4*)&g_part[(size_t)((srcI * N_GROUPS + g0 + 2) * 3 + 0) * EMBED];
        w[col4] = a2;
    }
}

// ---------------------------------------------------------------------------
// Kernel 1b: combine chunk partials -> group means.
// Grid = 512 blocks (group, src) x 256 threads (one float4 column each).
// ---------------------------------------------------------------------------
__global__ void __launch_bounds__(256) combine_kernel(
    const int* __restrict__ num_clips, const int* __restrict__ num_caps)
{
    const int b = blockIdx.x;
    const int g = b >> 1;
    const int srcI = b & 1;
    const int* __restrict__ cnt = (srcI == 0) ? num_clips : num_caps;
    float* __restrict__ dst = (srcI == 0) ? g_im_mean : g_s_mean;

    const int t = threadIdx.x;

    // start = sum of counts with index < g (block reduction, 1 count/thread)
    int contrib = (t < g) ? cnt[t] : 0;
    #pragma unroll
    for (int o = 16; o; o >>= 1) contrib += __shfl_xor_sync(0xFFFFFFFFu, contrib, o);
    __shared__ int ws[8];
    if ((t & 31) == 0) ws[t >> 5] = contrib;
    __syncthreads();
    int start = 0;
    #pragma unroll
    for (int u = 0; u < 8; u++) start += ws[u];

    const int n = cnt[g];
    const float inv = 1.0f / (float)n;
    const int nslots = ((start + n - 1) >> 4) - (start >> 4) + 1;   // 1..3

    const float4* basep = (const float4*)&g_part[(size_t)((srcI * N_GROUPS + g) * 3) * EMBED];
    float4 v = basep[t];
    if (nslots > 1) {
        float4 p1 = basep[VEC4 + t];
        v.x += p1.x; v.y += p1.y; v.z += p1.z; v.w += p1.w;
    }
    if (nslots > 2) {
        float4 p2 = basep[2 * VEC4 + t];
        v.x += p2.x; v.y += p2.y; v.z += p2.z; v.w += p2.w;
    }
    float4 o4;
    o4.x = v.x * inv; o4.y = v.y * inv; o4.z = v.z * inv; o4.w = v.w * inv;
    ((float4*)dst)[(size_t)g * VEC4 + t] = o4;
}

// ---------------------------------------------------------------------------
// Kernel 2: K-split GEMM partials, double-buffered smem.
// Grid (4,4,KSPLIT), 256 threads. 64x64 tile, K=128/split in chunks of 16,
// 4x4 microtile/thread. Prefetch chunk c+1 into regs while computing chunk c.
// ---------------------------------------------------------------------------
__global__ void __launch_bounds__(256) gemm_partial_kernel()
{
    __shared__ float As[2][16][68];
    __shared__ float Bs[2][16][68];

    const int tid = threadIdx.x;
    const int tx = tid & 15;
    const int ty = tid >> 4;
    const int bi = blockIdx.y * 64;
    const int bj = blockIdx.x * 64;
    const int kbase = blockIdx.z * (EMBED / KSPLIT);

    const int lr = tid >> 2;   // 0..63 : tile row to load
    const int lc = tid & 3;    // 0..3  : k-quad to load

    const float* Abase = &g_im_mean[(size_t)(bi + lr) * EMBED + kbase + lc * 4];
    const float* Bbase = &g_s_mean [(size_t)(bj + lr) * EMBED + kbase + lc * 4];

    float acc[4][4] = {};

    // preload chunk 0
    float4 a  = *(const float4*)Abase;
    float4 bv = *(const float4*)Bbase;
    As[0][lc * 4 + 0][lr] = a.x;  As[0][lc * 4 + 1][lr] = a.y;
    As[0][lc * 4 + 2][lr] = a.z;  As[0][lc * 4 + 3][lr] = a.w;
    Bs[0][lc * 4 + 0][lr] = bv.x; Bs[0][lc * 4 + 1][lr] = bv.y;
    Bs[0][lc * 4 + 2][lr] = bv.z; Bs[0][lc * 4 + 3][lr] = bv.w;
    __syncthreads();

    #pragma unroll
    for (int c = 0; c < 8; c++) {
        float4 an, bn;
        if (c < 7) {
            an = *(const float4*)(Abase + (c + 1) * 16);
            bn = *(const float4*)(Bbase + (c + 1) * 16);
        }
        const int cur = c & 1;
        #pragma unroll
        for (int kk = 0; kk < 16; kk++) {
            float4 av = *(const float4*)&As[cur][kk][ty * 4];
            float4 bw = *(const float4*)&Bs[cur][kk][tx * 4];
            acc[0][0] += av.x * bw.x; acc[0][1] += av.x * bw.y;
            acc[0][2] += av.x * bw.z; acc[0][3] += av.x * bw.w;
            acc[1][0] += av.y * bw.x; acc[1][1] += av.y * bw.y;
            acc[1][2] += av.y * bw.z; acc[1][3] += av.y * bw.w;
            acc[2][0] += av.z * bw.x; acc[2][1] += av.z * bw.y;
            acc[2][2] += av.z * bw.z; acc[2][3] += av.z * bw.w;
            acc[3][0] += av.w * bw.x; acc[3][1] += av.w * bw.y;
            acc[3][2] += av.w * bw.z; acc[3][3] += av.w * bw.w;
        }
        if (c < 7) {
            const int nb = (c + 1) & 1;
            As[nb][lc * 4 + 0][lr] = an.x;  As[nb][lc * 4 + 1][lr] = an.y;
            As[nb][lc * 4 + 2][lr] = an.z;  As[nb][lc * 4 + 3][lr] = an.w;
            Bs[nb][lc * 4 + 0][lr] = bn.x;  Bs[nb][lc * 4 + 1][lr] = bn.y;
            Bs[nb][lc * 4 + 2][lr] = bn.z;  Bs[nb][lc * 4 + 3][lr] = bn.w;
            __syncthreads();
        }
    }

    float* outp = g_Spart + (size_t)blockIdx.z * NPART;
    #pragma unroll
    for (int i = 0; i < 4; i++) {
        float4 v;
        v.x = acc[i][0]; v.y = acc[i][1]; v.z = acc[i][2]; v.w = acc[i][3];
        *(float4*)&outp[(size_t)(bi + ty * 4 + i) * N_GROUPS + bj + tx * 4] = v;
    }
}

// ---------------------------------------------------------------------------
// Kernel 3: fused K-split reduce + diag + hinge loss.
// Grid 64 blocks x 256 threads; last-block-arrival final reduction.
// ---------------------------------------------------------------------------
__global__ void __launch_bounds__(256) fused_loss_kernel(float* __restrict__ out)
{
    __shared__ float diag_s[N_GROUPS];
    __shared__ float red[8];
    __shared__ int is_last;

    const int t = threadIdx.x;
    const int b = blockIdx.x;

    // diag[t] = sum_z Spart[z][t*257]
    {
        float d = 0.f;
        #pragma unroll
        for (int z = 0; z < KSPLIT; z++)
            d += g_Spart[(size_t)z * NPART + t * (N_GROUPS + 1)];
        diag_s[t] = d;
    }
    __syncthreads();

    // this thread's float4 of S
    const int q = b * 256 + t;          // 0..16383
    float4 v = make_float4(0.f, 0.f, 0.f, 0.f);
    #pragma unroll
    for (int z = 0; z < KSPLIT; z++) {
        float4 p = *(const float4*)&g_Spart[(size_t)z * NPART + q * 4];
        v.x += p.x; v.y += p.y; v.z += p.z; v.w += p.w;
    }

    const int i = q >> 6;
    const int j0 = (q & 63) * 4;
    const float di = diag_s[i];
    float vv[4] = {v.x, v.y, v.z, v.w};
    float sum = 0.f;
    #pragma unroll
    for (int c = 0; c < 4; c++) {
        int j = j0 + c;
        if (j != i)
            sum += fmaxf(vv[c] - di, 0.f) + fmaxf(vv[c] - diag_s[j], 0.f);
    }

    #pragma unroll
    for (int o = 16; o; o >>= 1) sum += __shfl_xor_sync(0xFFFFFFFFu, sum, o);
    if ((t & 31) == 0) red[t >> 5] = sum;
    __syncthreads();

    if (t == 0) {
        float bs = red[0] + red[1] + red[2] + red[3]
                 + red[4] + red[5] + red[6] + red[7];
        g_loss_part[b] = bs;
        __threadfence();
        int old = atomicAdd(&g_count, 1);
        is_last = (old == 63) ? 1 : 0;
    }
    __syncthreads();

    if (is_last) {
        if (t < 64) {
            float v2 = __ldcg(&g_loss_part[t]);   // L2-coherent read of other blocks' partials
            #pragma unroll
            for (int o = 16; o; o >>= 1) v2 += __shfl_xor_sync(0xFFFFFFFFu, v2, o);
            if (t == 0)  red[0] = v2;    // warp 0 sum (partials 0..31)
            if (t == 32) red[1] = v2;    // warp 1 sum (partials 32..63)
        }
        __syncthreads();
        if (t == 0) {
            out[0] = red[0] + red[1];
            g_count = 0;                 // reset for next replay
        }
    }
}

extern "C" void kernel_launch(void* const* d_in, const int* in_sizes, int n_in,
                              void* d_out, int out_size)
{
    const float* im        = (const float*)d_in[0];
    const float* s         = (const float*)d_in[1];
    const int*   num_clips = (const int*)d_in[2];
    const int*   num_caps  = (const int*)d_in[3];
    float* out = (float*)d_out;

    segchunk_kernel<<<NCHUNK * 8, 64>>>(im, s, num_clips, num_caps);
    combine_kernel<<<N_GROUPS * 2, 256>>>(num_clips, num_caps);
    gemm_partial_kernel<<<dim3(4, 4, KSPLIT), 256>>>();
    fused_loss_kernel<<<64, 256>>>(out);
}